// round 2
// baseline (speedup 1.0000x reference)
#include <cuda_runtime.h>

#define BB 2
#define NN 16384
#define CC 64
#define JJ 16
#define OO 128
#define TP 32
#define PSTR 36   // proj row stride in floats (144B, 16B-aligned)

// Duplicated transposed weight: [j][c][o][2] (each weight stored twice for
// direct f32x2 broadcast operands). 1M floats = 4MB.
__device__ float g_Wd[JJ * CC * OO * 2];

__global__ void wt_dup_kernel(const float* __restrict__ w) {
    int i = blockIdx.x * 256 + threadIdx.x;   // 262144 total
    int o = (i >> 1) & 127;
    int c = (i >> 8) & 63;
    int j = i >> 14;
    g_Wd[i] = w[(o * CC + c) * JJ + j];
}

__device__ __forceinline__ void ffma2(unsigned long long& a, unsigned long long x, unsigned long long y) {
    asm("fma.rn.f32x2 %0, %1, %2, %0;" : "+l"(a) : "l"(x), "l"(y));
}
__device__ __forceinline__ float2 up2(unsigned long long v) {
    float2 r; asm("mov.b64 {%0, %1}, %2;" : "=f"(r.x), "=f"(r.y) : "l"(v)); return r;
}

__global__ __launch_bounds__(128, 4) void sconv_kernel(
    const float* __restrict__ x, const int* __restrict__ adj, float* __restrict__ out)
{
    __shared__ __align__(16) float proj[2][CC * PSTR];   // double-buffered [c][p]
    __shared__ int adjS[TP * JJ];

    const int tid = threadIdx.x;
    const int bx = blockIdx.x;
    const int b  = bx >> 9;                 // 512 blocks per batch
    const int n0 = (bx & 511) << 5;         // 32 points per block
    const float* xb = x + ((size_t)b * NN) * CC;

    // stage-1 mapping: 4 lanes per point, 16 channels per lane
    const int p_ = tid >> 2;
    const int l  = tid & 3;
    const int c0 = l << 4;
    // stage-2 mapping: 8 points per warp, 4 output channels per thread
    const int pq = tid >> 5;
    const int o0 = (tid & 31) << 2;

    // ---- adjacency preload (skip self column 0) ----
    {
        int base = (b * NN + n0) * 17;
        #pragma unroll
        for (int i = 0; i < 4; i++) {
            int idx = tid + 128 * i;          // 512 ints
            int p = idx >> 4, jj = idx & 15;
            adjS[idx] = adj[base + p * 17 + 1 + jj];
        }
    }

    // ---- center values: held in registers for all j (no smem) ----
    float ce[16];
    {
        const float4* cp = (const float4*)(xb + (n0 + p_) * CC + c0);
        #pragma unroll
        for (int q = 0; q < 4; q++) {
            float4 v = cp[q];
            ce[4*q+0] = v.x; ce[4*q+1] = v.y; ce[4*q+2] = v.z; ce[4*q+3] = v.w;
        }
    }
    __syncthreads();   // adjS ready

    // ---- stage-1 helper (gather neighbor jj, write proj buffer) ----
    auto stage1 = [&](int jj) {
        int g = adjS[p_ * JJ + jj];
        const float4* nb = (const float4*)(xb + (size_t)g * CC) + l * 4;
        float d[16];
        float ssq = 0.f;
        #pragma unroll
        for (int q = 0; q < 4; q++) {
            float4 nv = nb[q];
            d[4*q+0] = nv.x - ce[4*q+0]; d[4*q+1] = nv.y - ce[4*q+1];
            d[4*q+2] = nv.z - ce[4*q+2]; d[4*q+3] = nv.w - ce[4*q+3];
        }
        #pragma unroll
        for (int q = 0; q < 16; q++) ssq = fmaf(d[q], d[q], ssq);
        ssq += __shfl_xor_sync(0xffffffffu, ssq, 1);
        ssq += __shfl_xor_sync(0xffffffffu, ssq, 2);
        float s = rsqrtf(2.0f * ssq);   // 1/(sqrt2 * ||diff||)
        float* pr = proj[jj & 1];
        #pragma unroll
        for (int qq = 0; qq < 16; qq++) {
            int q = (qq + 4 * l) & 15;   // rotation: 4-way -> 2-way store conflicts
            pr[(c0 + q) * PSTR + p_] = d[q] * s;
        }
    };

    float m[32];
    #pragma unroll
    for (int i = 0; i < 32; i++) m[i] = 0.0f;   // relu+max -> init 0

    stage1(0);
    __syncthreads();

    for (int j = 0; j < JJ; j++) {
        // ---- stage 2: 4x8 register tile, f32x2 packed ----
        unsigned long long acc[16];
        #pragma unroll
        for (int i = 0; i < 16; i++) acc[i] = 0ULL;

        const ulonglong2* Wj = (const ulonglong2*)(g_Wd + (j << 14)) + ((tid & 31) << 1);
        const float* pbuf = proj[j & 1] + pq * 8;
        #pragma unroll 4
        for (int c = 0; c < CC; c++) {
            ulonglong2 wa = Wj[c * 64];          // dup pairs for o0, o0+1 (LDG.128)
            ulonglong2 wb = Wj[c * 64 + 1];      // dup pairs for o0+2, o0+3
            const ulonglong2* r = (const ulonglong2*)(pbuf + c * PSTR);
            ulonglong2 u0 = r[0], u1 = r[1];     // 8 points, broadcast LDS.128 x2
            ffma2(acc[0],  wa.x, u0.x); ffma2(acc[1],  wa.x, u0.y);
            ffma2(acc[2],  wa.x, u1.x); ffma2(acc[3],  wa.x, u1.y);
            ffma2(acc[4],  wa.y, u0.x); ffma2(acc[5],  wa.y, u0.y);
            ffma2(acc[6],  wa.y, u1.x); ffma2(acc[7],  wa.y, u1.y);
            ffma2(acc[8],  wb.x, u0.x); ffma2(acc[9],  wb.x, u0.y);
            ffma2(acc[10], wb.x, u1.x); ffma2(acc[11], wb.x, u1.y);
            ffma2(acc[12], wb.y, u0.x); ffma2(acc[13], wb.y, u0.y);
            ffma2(acc[14], wb.y, u1.x); ffma2(acc[15], wb.y, u1.y);
        }
        #pragma unroll
        for (int i = 0; i < 16; i++) {
            float2 v = up2(acc[i]);
            int oi = i >> 2, pp = i & 3;
            m[oi * 8 + pp * 2]     = fmaxf(m[oi * 8 + pp * 2],     v.x);
            m[oi * 8 + pp * 2 + 1] = fmaxf(m[oi * 8 + pp * 2 + 1], v.y);
        }

        // ---- stage 1 for j+1 into the other buffer ----
        if (j + 1 < JJ) stage1(j + 1);
        __syncthreads();
    }

    // ---- write out[b][o][n]: 4 rows x 8 consecutive n per thread ----
    float* op = out + ((size_t)(b * OO + o0) * NN) + n0 + pq * 8;
    #pragma unroll
    for (int oi = 0; oi < 4; oi++) {
        float4* v = (float4*)(op + (size_t)oi * NN);
        v[0] = make_float4(m[oi*8+0], m[oi*8+1], m[oi*8+2], m[oi*8+3]);
        v[1] = make_float4(m[oi*8+4], m[oi*8+5], m[oi*8+6], m[oi*8+7]);
    }
}

extern "C" void kernel_launch(void* const* d_in, const int* in_sizes, int n_in,
                              void* d_out, int out_size) {
    const float* x   = (const float*)d_in[0];
    const int*   adj = (const int*)d_in[1];
    const float* w   = (const float*)d_in[2];
    float* out = (float*)d_out;

    wt_dup_kernel<<<1024, 256>>>(w);            // trivial cost, same stream -> ordered
    sconv_kernel<<<1024, 128>>>(x, adj, out);
}